// round 13
// baseline (speedup 1.0000x reference)
#include <cuda_runtime.h>
#include <cuda_fp16.h>
#include <cstdint>

// Problem constants
#define H_DIM 1024
#define N_EXP 8
#define N_TOK 8192      // B*S
#define BM 128
#define BN 128
#define KT 64                 // k-elements per smem tile (fp16): 128B rows
#define NKT (H_DIM / KT)      // 16
#define NTHREADS 256

// SMEM layout (dynamic)
#define SM_TOK    0                       // 128 ints
#define SM_GATE   512                     // 128 floats
#define SM_TILES  1024
#define TILE_BYTES 16384                  // 128 rows x 128B
#define BUF_BYTES (2 * TILE_BYTES)        // Ah, Wh
#define SMEM_TOTAL (SM_TILES + 2 * BUF_BYTES)   // 66560

// -------- scratch (allocation-free: __device__ globals) --------
__device__ int   d_counts[N_EXP];
__device__ int   d_tok [N_EXP][N_TOK];
__device__ float d_gate[N_EXP][N_TOK];          // sign encodes slot: + => top1, - => top2
__device__ __half d_xh[(size_t)N_TOK * H_DIM];
__device__ __half d_wh[(size_t)N_EXP * H_DIM * H_DIM];
__device__ float d_partial[(size_t)N_TOK * 2 * H_DIM];   // 64 MB

// ---------------- PTX helpers (baseline sm_80+ features only) ----
__device__ __forceinline__ uint32_t smem_to_u32(const void* p) {
    uint32_t a;
    asm("{ .reg .u64 t; cvta.to.shared.u64 t, %1; cvt.u32.u64 %0, t; }"
        : "=r"(a) : "l"(p));
    return a;
}
__device__ __forceinline__ void cp_async16(uint32_t dst, const void* src, uint32_t src_size) {
    asm volatile("cp.async.cg.shared.global [%0], [%1], 16, %2;"
                 :: "r"(dst), "l"(src), "r"(src_size) : "memory");
}
__device__ __forceinline__ void cp_commit() {
    asm volatile("cp.async.commit_group;" ::: "memory");
}
__device__ __forceinline__ void cp_wait1() {
    asm volatile("cp.async.wait_group 1;" ::: "memory");
}
__device__ __forceinline__ void cp_wait0() {
    asm volatile("cp.async.wait_group 0;" ::: "memory");
}
__device__ __forceinline__ void ldsm_x4(uint32_t* r, uint32_t addr) {
    asm volatile("ldmatrix.sync.aligned.m8n8.x4.shared.b16 {%0,%1,%2,%3}, [%4];"
                 : "=r"(r[0]), "=r"(r[1]), "=r"(r[2]), "=r"(r[3]) : "r"(addr));
}
__device__ __forceinline__ void mma_fp16(float* d, const uint32_t* a, const uint32_t* b) {
    asm volatile("mma.sync.aligned.m16n8k16.row.col.f32.f16.f16.f32 "
                 "{%0,%1,%2,%3}, {%4,%5,%6,%7}, {%8,%9}, {%0,%1,%2,%3};"
                 : "+f"(d[0]), "+f"(d[1]), "+f"(d[2]), "+f"(d[3])
                 : "r"(a[0]), "r"(a[1]), "r"(a[2]), "r"(a[3]),
                   "r"(b[0]), "r"(b[1]));
}

// ---------------- kernel 0: zero the expert counters -------------
__global__ void moe_zero_counts() {
    if (threadIdx.x < N_EXP) d_counts[threadIdx.x] = 0;
}

// ---------------- kernel 1: fused prep (convert_w + gate) --------
// blocks [0, 8192): w -> fp16 (float4 granularity)
// blocks [8192, 9216): gate + x -> fp16 (one warp per token)
#define PREP_W_BLOCKS 8192
#define PREP_G_BLOCKS (N_TOK / 8)
__global__ void moe_prep_kernel(const float4* __restrict__ ew4,
                                const float* __restrict__ x,
                                const float* __restrict__ gw,
                                const float* __restrict__ gb) {
    if (blockIdx.x < PREP_W_BLOCKS) {
        // ---- convert w ----
        int i = blockIdx.x * 256 + threadIdx.x;   // < 2,097,152
        float4 v = ew4[i];
        __half2* hi = (__half2*)d_wh;
        hi[i * 2 + 0] = __floats2half2_rn(v.x, v.y);
        hi[i * 2 + 1] = __floats2half2_rn(v.z, v.w);
        return;
    }
    // ---- gate + x convert: one warp per token ----
    int tok  = ((blockIdx.x - PREP_W_BLOCKS) * 256 + threadIdx.x) >> 5;
    int lane = threadIdx.x & 31;
    if (tok >= N_TOK) return;

    const float4* xr4 = (const float4*)(x + (size_t)tok * H_DIM);
    const float4* gw4 = (const float4*)gw;
    __half2* xh2 = (__half2*)(d_xh + (size_t)tok * H_DIM);

    float acc[N_EXP];
#pragma unroll
    for (int e = 0; e < N_EXP; e++) acc[e] = 0.f;

    for (int h4 = lane; h4 < H_DIM / 4; h4 += 32) {
        float4 v = xr4[h4];
        xh2[h4 * 2 + 0] = __floats2half2_rn(v.x, v.y);
        xh2[h4 * 2 + 1] = __floats2half2_rn(v.z, v.w);
#pragma unroll
        for (int e = 0; e < N_EXP; e++) {
            float4 g = gw4[e * (H_DIM / 4) + h4];
            acc[e] += v.x * g.x + v.y * g.y + v.z * g.z + v.w * g.w;
        }
    }
#pragma unroll
    for (int e = 0; e < N_EXP; e++) {
#pragma unroll
        for (int off = 16; off; off >>= 1)
            acc[e] += __shfl_xor_sync(0xffffffffu, acc[e], off);
    }
    if (lane == 0) {
        float logit[N_EXP], mx = -1e30f;
#pragma unroll
        for (int e = 0; e < N_EXP; e++) { logit[e] = acc[e] + gb[e]; mx = fmaxf(mx, logit[e]); }
        float p[N_EXP], s = 0.f;
#pragma unroll
        for (int e = 0; e < N_EXP; e++) { p[e] = __expf(logit[e] - mx); s += p[e]; }
        float inv = 1.f / s;
#pragma unroll
        for (int e = 0; e < N_EXP; e++) p[e] *= inv;
        int i0 = 0;
#pragma unroll
        for (int e = 1; e < N_EXP; e++) if (p[e] > p[i0]) i0 = e;
        int i1 = (i0 == 0) ? 1 : 0;
#pragma unroll
        for (int e = 0; e < N_EXP; e++) if (e != i0 && p[e] > p[i1]) i1 = e;

        int pos0 = atomicAdd(&d_counts[i0], 1);
        d_tok [i0][pos0] = tok;
        d_gate[i0][pos0] = p[i0];          // slot 0: positive
        int pos1 = atomicAdd(&d_counts[i1], 1);
        d_tok [i1][pos1] = tok;
        d_gate[i1][pos1] = -p[i1];         // slot 1: negative (sign = slot tag)
    }
}

// ---------------- kernel 2: HMMA grouped GEMM (fp16) -------------
__device__ __forceinline__ void issue_tile(uint32_t smem_u, int buf, int kt,
                                           const int* tok_s,
                                           const __half* whb,
                                           int n0, int tid) {
    const uint32_t base = smem_u + SM_TILES + buf * BUF_BYTES;
    const int kk = kt * KT;
#pragma unroll
    for (int it = 0; it < 4; it++) {
        const int idx = tid + it * NTHREADS;   // 0..1023
        const int row = idx >> 3;              // 0..127
        const int chunk = idx & 7;             // 16B chunk in 128B row
        const uint32_t sw = (uint32_t)(row * 128 + ((chunk * 16) ^ ((row & 7) << 4)));
        const int t = tok_s[row];
        const size_t xo = (size_t)(t < 0 ? 0 : t) * H_DIM + kk + chunk * 8;
        const uint32_t ok = (t >= 0) ? 16u : 0u;
        cp_async16(base + sw, d_xh + xo, ok);
        const size_t wo = (size_t)(n0 + row) * H_DIM + kk + chunk * 8;
        cp_async16(base + TILE_BYTES + sw, whb + wo, 16u);
    }
}

__global__ void __launch_bounds__(NTHREADS, 2)
moe_gemm_mma(const float* __restrict__ eb) {
    extern __shared__ __align__(1024) char smem[];
    const int e   = blockIdx.z;
    const int cnt = d_counts[e];
    const int m0  = blockIdx.y * BM;
    if (m0 >= cnt) return;
    const int n0  = blockIdx.x * BN;
    const int tid = threadIdx.x;
    const uint32_t smem_u = smem_to_u32(smem);

    int*   tok_s = (int*)(smem + SM_TOK);
    float* gw_s  = (float*)(smem + SM_GATE);
    if (tid < BM) {
        int m = m0 + tid;
        tok_s[tid] = (m < cnt) ? d_tok [e][m] : -1;
        gw_s [tid] = (m < cnt) ? d_gate[e][m] : 0.f;
    }
    __syncthreads();

    const __half* whb = d_wh + (size_t)e * H_DIM * H_DIM;

    // warp mapping: 4 warps in m, 2 in n
    const int lane = tid & 31;
    const int wm = (tid >> 5) & 3;        // m warp: 32 rows
    const int wn = (tid >> 5) >> 2;       // n warp: 64 cols

    const int ar   = lane & 15;
    const int ak   = (lane >> 4) * 16;
    const int xora = (ar & 7) << 4;
    const int br   = (lane & 7) + ((lane >> 4) << 3);
    const int bk   = ((lane >> 3) & 1) * 16;
    const int xorb = (br & 7) << 4;

    uint32_t aoff[2], boff[4];
#pragma unroll
    for (int mt = 0; mt < 2; mt++)
        aoff[mt] = (uint32_t)((wm * 32 + mt * 16 + ar) * 128);
#pragma unroll
    for (int nt2 = 0; nt2 < 4; nt2++)
        boff[nt2] = (uint32_t)((wn * 64 + nt2 * 16 + br) * 128);

    float acc[2][8][4];
#pragma unroll
    for (int i = 0; i < 2; i++)
#pragma unroll
        for (int j = 0; j < 8; j++)
#pragma unroll
            for (int q = 0; q < 4; q++) acc[i][j][q] = 0.f;

    // prologue
    issue_tile(smem_u, 0, 0, tok_s, whb, n0, tid);
    cp_commit();

    for (int kt = 0; kt < NKT; kt++) {
        const int cur = kt & 1;
        if (kt + 1 < NKT) {
            issue_tile(smem_u, cur ^ 1, kt + 1, tok_s, whb, n0, tid);
            cp_commit();
            cp_wait1();
        } else {
            cp_wait0();
        }
        __syncthreads();

        const uint32_t abase = smem_u + SM_TILES + cur * BUF_BYTES;
        const uint32_t bbase = abase + TILE_BYTES;
#pragma unroll
        for (int kkq = 0; kkq < KT / 16; kkq++) {   // 4 k16 steps
            const uint32_t akb = (uint32_t)((kkq * 32 + ak) ^ xora);
            const uint32_t bkb = (uint32_t)((kkq * 32 + bk) ^ xorb);
            uint32_t ah[2][4], bh[4][4];
#pragma unroll
            for (int mt = 0; mt < 2; mt++)
                ldsm_x4(ah[mt], abase + aoff[mt] + akb);
#pragma unroll
            for (int nt2 = 0; nt2 < 4; nt2++)
                ldsm_x4(bh[nt2], bbase + boff[nt2] + bkb);
#pragma unroll
            for (int mt = 0; mt < 2; mt++)
#pragma unroll
                for (int nt2 = 0; nt2 < 4; nt2++) {
                    mma_fp16(acc[mt][2 * nt2 + 0], ah[mt], &bh[nt2][0]);
                    mma_fp16(acc[mt][2 * nt2 + 1], ah[mt], &bh[nt2][2]);
                }
        }
        __syncthreads();
    }

    // epilogue: y = |g| * (acc + bias) -> plain stores into d_partial slot
    // (slot = signbit of stored gate; every real (token, slot) written exactly once)
#pragma unroll
    for (int mt = 0; mt < 2; mt++) {
        const int r0 = wm * 32 + mt * 16 + (lane >> 2);
        const int r1 = r0 + 8;
        const int t0 = tok_s[r0];
        const int t1 = tok_s[r1];
        const float gs0 = gw_s[r0];
        const float gs1 = gw_s[r1];
        const float g0 = fabsf(gs0), g1 = fabsf(gs1);
        float* p0 = nullptr;
        float* p1 = nullptr;
        if (t0 >= 0) p0 = d_partial + ((size_t)t0 * 2 + (gs0 < 0.f ? 1 : 0)) * H_DIM;
        if (t1 >= 0) p1 = d_partial + ((size_t)t1 * 2 + (gs1 < 0.f ? 1 : 0)) * H_DIM;
#pragma unroll
        for (int nt = 0; nt < 8; nt++) {
            const int col = n0 + wn * 64 + nt * 8 + 2 * (lane & 3);
            const float b0 = eb[e * H_DIM + col];
            const float b1 = eb[e * H_DIM + col + 1];
            if (p0) {
                float2 v = make_float2(g0 * (acc[mt][nt][0] + b0),
                                       g0 * (acc[mt][nt][1] + b1));
                *(float2*)(p0 + col) = v;
            }
            if (p1) {
                float2 v = make_float2(g1 * (acc[mt][nt][2] + b0),
                                       g1 * (acc[mt][nt][3] + b1));
                *(float2*)(p1 + col) = v;
            }
        }
    }
}

// ---------------- kernel 3: gather (partial[0] + partial[1]) -----
__global__ void moe_gather_kernel(float4* __restrict__ out4) {
    size_t i = (size_t)blockIdx.x * blockDim.x + threadIdx.x;  // < 2,097,152
    size_t t = i >> 8;            // token  (H_DIM/4 = 256 float4 per row)
    size_t j = i & 255;
    const float4* p = (const float4*)d_partial;
    float4 a = p[t * 512 + j];
    float4 b = p[t * 512 + 256 + j];
    out4[i] = make_float4(a.x + b.x, a.y + b.y, a.z + b.z, a.w + b.w);
}

// ------------------------- launcher ------------------------------
extern "C" void kernel_launch(void* const* d_in, const int* in_sizes, int n_in,
                              void* d_out, int out_size) {
    const float* x   = (const float*)d_in[0];  // [4,2048,1024]
    const float* gw  = (const float*)d_in[1];  // [8,1024]
    const float* gb  = (const float*)d_in[2];  // [8]
    const float* ew  = (const float*)d_in[3];  // [8,1024,1024]
    const float* eb  = (const float*)d_in[4];  // [8,1024]
    float* out = (float*)d_out;

    cudaFuncSetAttribute(moe_gemm_mma,
                         cudaFuncAttributeMaxDynamicSharedMemorySize, SMEM_TOTAL);

    // 0) zero expert counters (gate appends atomically)
    moe_zero_counts<<<1, 32>>>();
    // 1) fused prep: w->fp16 conversion overlapped with gate + x->fp16
    moe_prep_kernel<<<PREP_W_BLOCKS + PREP_G_BLOCKS, 256>>>(
        (const float4*)ew, x, gw, gb);
    // 2) HMMA grouped GEMM -> d_partial (plain stores, no atomics)
    {
        dim3 grid(H_DIM / BN, N_TOK / BM, N_EXP);  // (8, 64, 8)
        moe_gemm_mma<<<grid, NTHREADS, SMEM_TOTAL>>>(eb);
    }
    // 3) gather: out = partial[slot0] + partial[slot1]
    {
        int n4 = N_TOK * H_DIM / 4;
        moe_gather_kernel<<<n4 / 256, 256>>>((float4*)out);
    }
}

// round 14
// speedup vs baseline: 1.0235x; 1.0235x over previous
#include <cuda_runtime.h>
#include <cuda_fp16.h>
#include <cstdint>

// Problem constants
#define H_DIM 1024
#define N_EXP 8
#define N_TOK 8192      // B*S
#define BM 128
#define BN 128
#define KT 64                 // k-elements per smem tile (fp16): 128B rows
#define NKT (H_DIM / KT)      // 16
#define NTHREADS 256
#define NSTAGE 3

// SMEM layout (dynamic)
#define SM_TOK    0                       // 128 ints
#define SM_GATE   512                     // 128 floats
#define SM_TILES  1024
#define TILE_BYTES 16384                  // 128 rows x 128B
#define BUF_BYTES (2 * TILE_BYTES)        // Ah, Wh
#define SMEM_TOTAL (SM_TILES + NSTAGE * BUF_BYTES)   // 99328

// -------- scratch (allocation-free: __device__ globals) --------
__device__ int   d_counts[N_EXP];
__device__ int   d_tok [N_EXP][N_TOK];
__device__ float d_gate[N_EXP][N_TOK];
__device__ __half d_xh[(size_t)N_TOK * H_DIM];
__device__ __half d_wh[(size_t)N_EXP * H_DIM * H_DIM];

// ---------------- PTX helpers (baseline sm_80+ features only) ----
__device__ __forceinline__ uint32_t smem_to_u32(const void* p) {
    uint32_t a;
    asm("{ .reg .u64 t; cvta.to.shared.u64 t, %1; cvt.u32.u64 %0, t; }"
        : "=r"(a) : "l"(p));
    return a;
}
__device__ __forceinline__ void cp_async16(uint32_t dst, const void* src, uint32_t src_size) {
    asm volatile("cp.async.cg.shared.global [%0], [%1], 16, %2;"
                 :: "r"(dst), "l"(src), "r"(src_size) : "memory");
}
__device__ __forceinline__ void cp_commit() {
    asm volatile("cp.async.commit_group;" ::: "memory");
}
__device__ __forceinline__ void cp_wait1() {
    asm volatile("cp.async.wait_group 1;" ::: "memory");
}
__device__ __forceinline__ void cp_wait0() {
    asm volatile("cp.async.wait_group 0;" ::: "memory");
}
__device__ __forceinline__ void ldsm_x4(uint32_t* r, uint32_t addr) {
    asm volatile("ldmatrix.sync.aligned.m8n8.x4.shared.b16 {%0,%1,%2,%3}, [%4];"
                 : "=r"(r[0]), "=r"(r[1]), "=r"(r[2]), "=r"(r[3]) : "r"(addr));
}
__device__ __forceinline__ void mma_fp16(float* d, const uint32_t* a, const uint32_t* b) {
    asm volatile("mma.sync.aligned.m16n8k16.row.col.f32.f16.f16.f32 "
                 "{%0,%1,%2,%3}, {%4,%5,%6,%7}, {%8,%9}, {%0,%1,%2,%3};"
                 : "+f"(d[0]), "+f"(d[1]), "+f"(d[2]), "+f"(d[3])
                 : "r"(a[0]), "r"(a[1]), "r"(a[2]), "r"(a[3]),
                   "r"(b[0]), "r"(b[1]));
}

// ---------------- kernel 0: zero the expert counters -------------
__global__ void moe_zero_counts() {
    if (threadIdx.x < N_EXP) d_counts[threadIdx.x] = 0;
}

// ---------------- kernel 1: mega prep -----------------------------
// blocks [0, 8192):      zero out (float4)
// blocks [8192, 16384):  w -> fp16 (float4)
// blocks [16384, 17408): gate + x -> fp16 (one warp per token)
#define PREP_Z_BLOCKS 8192
#define PREP_W_BLOCKS 8192
#define PREP_G_BLOCKS (N_TOK / 8)
__global__ void moe_prep_kernel(float4* __restrict__ out4,
                                const float4* __restrict__ ew4,
                                const float* __restrict__ x,
                                const float* __restrict__ gw,
                                const float* __restrict__ gb) {
    if (blockIdx.x < PREP_Z_BLOCKS) {
        // ---- zero output ----
        int i = blockIdx.x * 256 + threadIdx.x;   // < 2,097,152
        out4[i] = make_float4(0.f, 0.f, 0.f, 0.f);
        return;
    }
    if (blockIdx.x < PREP_Z_BLOCKS + PREP_W_BLOCKS) {
        // ---- convert w ----
        int i = (blockIdx.x - PREP_Z_BLOCKS) * 256 + threadIdx.x;
        float4 v = ew4[i];
        __half2* hi = (__half2*)d_wh;
        hi[i * 2 + 0] = __floats2half2_rn(v.x, v.y);
        hi[i * 2 + 1] = __floats2half2_rn(v.z, v.w);
        return;
    }
    // ---- gate + x convert: one warp per token ----
    int tok  = ((blockIdx.x - PREP_Z_BLOCKS - PREP_W_BLOCKS) * 256 + threadIdx.x) >> 5;
    int lane = threadIdx.x & 31;
    if (tok >= N_TOK) return;

    const float4* xr4 = (const float4*)(x + (size_t)tok * H_DIM);
    const float4* gw4 = (const float4*)gw;
    __half2* xh2 = (__half2*)(d_xh + (size_t)tok * H_DIM);

    float acc[N_EXP];
#pragma unroll
    for (int e = 0; e < N_EXP; e++) acc[e] = 0.f;

    for (int h4 = lane; h4 < H_DIM / 4; h4 += 32) {
        float4 v = xr4[h4];
        xh2[h4 * 2 + 0] = __floats2half2_rn(v.x, v.y);
        xh2[h4 * 2 + 1] = __floats2half2_rn(v.z, v.w);
#pragma unroll
        for (int e = 0; e < N_EXP; e++) {
            float4 g = gw4[e * (H_DIM / 4) + h4];
            acc[e] += v.x * g.x + v.y * g.y + v.z * g.z + v.w * g.w;
        }
    }
#pragma unroll
    for (int e = 0; e < N_EXP; e++) {
#pragma unroll
        for (int off = 16; off; off >>= 1)
            acc[e] += __shfl_xor_sync(0xffffffffu, acc[e], off);
    }
    if (lane == 0) {
        float logit[N_EXP], mx = -1e30f;
#pragma unroll
        for (int e = 0; e < N_EXP; e++) { logit[e] = acc[e] + gb[e]; mx = fmaxf(mx, logit[e]); }
        float p[N_EXP], s = 0.f;
#pragma unroll
        for (int e = 0; e < N_EXP; e++) { p[e] = __expf(logit[e] - mx); s += p[e]; }
        float inv = 1.f / s;
#pragma unroll
        for (int e = 0; e < N_EXP; e++) p[e] *= inv;
        int i0 = 0;
#pragma unroll
        for (int e = 1; e < N_EXP; e++) if (p[e] > p[i0]) i0 = e;
        int i1 = (i0 == 0) ? 1 : 0;
#pragma unroll
        for (int e = 0; e < N_EXP; e++) if (e != i0 && p[e] > p[i1]) i1 = e;

        int pos0 = atomicAdd(&d_counts[i0], 1);
        d_tok [i0][pos0] = tok;
        d_gate[i0][pos0] = p[i0];
        int pos1 = atomicAdd(&d_counts[i1], 1);
        d_tok [i1][pos1] = tok;
        d_gate[i1][pos1] = p[i1];
    }
}

// ---------------- kernel 2: HMMA grouped GEMM (fp16, 3-stage) ----
__device__ __forceinline__ void issue_tile(uint32_t smem_u, int buf, int kt,
                                           const int* tok_s,
                                           const __half* whb,
                                           int n0, int tid) {
    const uint32_t base = smem_u + SM_TILES + buf * BUF_BYTES;
    const int kk = kt * KT;
#pragma unroll
    for (int it = 0; it < 4; it++) {
        const int idx = tid + it * NTHREADS;   // 0..1023
        const int row = idx >> 3;              // 0..127
        const int chunk = idx & 7;             // 16B chunk in 128B row
        const uint32_t sw = (uint32_t)(row * 128 + ((chunk * 16) ^ ((row & 7) << 4)));
        const int t = tok_s[row];
        const size_t xo = (size_t)(t < 0 ? 0 : t) * H_DIM + kk + chunk * 8;
        const uint32_t ok = (t >= 0) ? 16u : 0u;
        cp_async16(base + sw, d_xh + xo, ok);
        const size_t wo = (size_t)(n0 + row) * H_DIM + kk + chunk * 8;
        cp_async16(base + TILE_BYTES + sw, whb + wo, 16u);
    }
}

__global__ void __launch_bounds__(NTHREADS, 2)
moe_gemm_mma(const float* __restrict__ eb, float* __restrict__ out) {
    extern __shared__ __align__(1024) char smem[];
    const int e   = blockIdx.z;
    const int cnt = d_counts[e];
    const int m0  = blockIdx.y * BM;
    if (m0 >= cnt) return;
    const int n0  = blockIdx.x * BN;
    const int tid = threadIdx.x;
    const uint32_t smem_u = smem_to_u32(smem);

    int*   tok_s = (int*)(smem + SM_TOK);
    float* gw_s  = (float*)(smem + SM_GATE);
    if (tid < BM) {
        int m = m0 + tid;
        tok_s[tid] = (m < cnt) ? d_tok [e][m] : -1;
        gw_s [tid] = (m < cnt) ? d_gate[e][m] : 0.f;
    }
    __syncthreads();

    const __half* whb = d_wh + (size_t)e * H_DIM * H_DIM;

    // warp mapping: 4 warps in m, 2 in n
    const int lane = tid & 31;
    const int wm = (tid >> 5) & 3;        // m warp: 32 rows
    const int wn = (tid >> 5) >> 2;       // n warp: 64 cols

    const int ar   = lane & 15;
    const int ak   = (lane >> 4) * 16;
    const int xora = (ar & 7) << 4;
    const int br   = (lane & 7) + ((lane >> 4) << 3);
    const int bk   = ((lane >> 3) & 1) * 16;
    const int xorb = (br & 7) << 4;

    uint32_t aoff[2], boff[4];
#pragma unroll
    for (int mt = 0; mt < 2; mt++)
        aoff[mt] = (uint32_t)((wm * 32 + mt * 16 + ar) * 128);
#pragma unroll
    for (int nt2 = 0; nt2 < 4; nt2++)
        boff[nt2] = (uint32_t)((wn * 64 + nt2 * 16 + br) * 128);

    float acc[2][8][4];
#pragma unroll
    for (int i = 0; i < 2; i++)
#pragma unroll
        for (int j = 0; j < 8; j++)
#pragma unroll
            for (int q = 0; q < 4; q++) acc[i][j][q] = 0.f;

    // prologue: stages 0 and 1 in flight
    issue_tile(smem_u, 0, 0, tok_s, whb, n0, tid);
    cp_commit();
    issue_tile(smem_u, 1, 1, tok_s, whb, n0, tid);
    cp_commit();

    int buf = 0;          // kt % 3
    int nbuf = 2;         // (kt+2) % 3
#pragma unroll 1
    for (int kt = 0; kt < NKT; kt++) {
        if (kt < NKT - 1) cp_wait1(); else cp_wait0();
        __syncthreads();                        // tile kt visible; buf nbuf free
        if (kt + 2 < NKT) {
            issue_tile(smem_u, nbuf, kt + 2, tok_s, whb, n0, tid);
            cp_commit();
        }

        const uint32_t abase = smem_u + SM_TILES + buf * BUF_BYTES;
        const uint32_t bbase = abase + TILE_BYTES;
#pragma unroll
        for (int kkq = 0; kkq < KT / 16; kkq++) {   // 4 k16 steps
            const uint32_t akb = (uint32_t)((kkq * 32 + ak) ^ xora);
            const uint32_t bkb = (uint32_t)((kkq * 32 + bk) ^ xorb);
            uint32_t ah[2][4], bh[4][4];
#pragma unroll
            for (int mt = 0; mt < 2; mt++)
                ldsm_x4(ah[mt], abase + aoff[mt] + akb);
#pragma unroll
            for (int nt2 = 0; nt2 < 4; nt2++)
                ldsm_x4(bh[nt2], bbase + boff[nt2] + bkb);
#pragma unroll
            for (int mt = 0; mt < 2; mt++)
#pragma unroll
                for (int nt2 = 0; nt2 < 4; nt2++) {
                    mma_fp16(acc[mt][2 * nt2 + 0], ah[mt], &bh[nt2][0]);
                    mma_fp16(acc[mt][2 * nt2 + 1], ah[mt], &bh[nt2][2]);
                }
        }
        buf = (buf == 2) ? 0 : buf + 1;
        nbuf = (nbuf == 2) ? 0 : nbuf + 1;
    }

    // epilogue: y = gate * (acc + bias), atomic scatter per token row
#pragma unroll
    for (int mt = 0; mt < 2; mt++) {
        const int r0 = wm * 32 + mt * 16 + (lane >> 2);
        const int r1 = r0 + 8;
        const int t0 = tok_s[r0];
        const int t1 = tok_s[r1];
        const float g0 = gw_s[r0];
        const float g1 = gw_s[r1];
#pragma unroll
        for (int nt = 0; nt < 8; nt++) {
            const int col = n0 + wn * 64 + nt * 8 + 2 * (lane & 3);
            const float b0 = eb[e * H_DIM + col];
            const float b1 = eb[e * H_DIM + col + 1];
            if (t0 >= 0) {
                float* o = out + (size_t)t0 * H_DIM + col;
                atomicAdd(&o[0], g0 * (acc[mt][nt][0] + b0));
                atomicAdd(&o[1], g0 * (acc[mt][nt][1] + b1));
            }
            if (t1 >= 0) {
                float* o = out + (size_t)t1 * H_DIM + col;
                atomicAdd(&o[0], g1 * (acc[mt][nt][2] + b0));
                atomicAdd(&o[1], g1 * (acc[mt][nt][3] + b1));
            }
        }
    }
}

// ------------------------- launcher ------------------------------
extern "C" void kernel_launch(void* const* d_in, const int* in_sizes, int n_in,
                              void* d_out, int out_size) {
    const float* x   = (const float*)d_in[0];  // [4,2048,1024]
    const float* gw  = (const float*)d_in[1];  // [8,1024]
    const float* gb  = (const float*)d_in[2];  // [8]
    const float* ew  = (const float*)d_in[3];  // [8,1024,1024]
    const float* eb  = (const float*)d_in[4];  // [8,1024]
    float* out = (float*)d_out;

    cudaFuncSetAttribute(moe_gemm_mma,
                         cudaFuncAttributeMaxDynamicSharedMemorySize, SMEM_TOTAL);

    // 0) zero expert counters (gate appends atomically)
    moe_zero_counts<<<1, 32>>>();
    // 1) mega prep: zero out + w->fp16 + gate/x->fp16, all overlapped
    moe_prep_kernel<<<PREP_Z_BLOCKS + PREP_W_BLOCKS + PREP_G_BLOCKS, 256>>>(
        (float4*)out, (const float4*)ew, x, gw, gb);
    // 2) HMMA grouped GEMM (3-stage pipeline, atomic scatter epilogue)
    {
        dim3 grid(H_DIM / BN, N_TOK / BM, N_EXP);  // (8, 64, 8)
        moe_gemm_mma<<<grid, NTHREADS, SMEM_TOTAL>>>(eb, out);
    }
}